// round 1
// baseline (speedup 1.0000x reference)
#include <cuda_runtime.h>
#include <cstddef>

#define L_SEQ 4096
#define SDIM  384
#define DST   16
#define BATCH 4
#define M_TOT (BATCH * L_SEQ)      // 16384
#define P_TOT (2 * SDIM + 2 * DST) // 800

// ---------------- scratch (no allocations allowed) ----------------
__device__ float g_xin[M_TOT * SDIM];
__device__ float g_dsp[M_TOT * SDIM];
__device__ float g_Bm [M_TOT * DST];
__device__ float g_Cm [M_TOT * DST];
__device__ float g_y  [M_TOT * SDIM];

__device__ __forceinline__ float softplusf(float z) {
    if (z > 20.f) return z;
    return log1pf(__expf(z));
}

// ================= proj GEMM: (B*L,384) @ (384,800)^T + bias, fused split =================
// A (seq) element [m][k] = x[b*384*4096 + k*4096 + l]  (m = b*4096 + l)
// B element [k][n] = W_proj[n*384 + k]
// BM=128, BN=64, BK=16, 256 threads, 8x4 micro-tile
__global__ __launch_bounds__(256) void proj_kernel(
    const float* __restrict__ x,  const float* __restrict__ Wp,
    const float* __restrict__ bp, const float* __restrict__ dtb)
{
    __shared__ float As[16][128];
    __shared__ float Bs[16][68];

    const int tid = threadIdx.x;
    const int tx  = tid & 15;   // m direction, 8 each
    const int ty  = tid >> 4;   // n direction, 4 each
    const int m0  = blockIdx.x * 128;
    const int n0  = blockIdx.y * 64;
    const int b   = m0 >> 12;        // 128 | 4096, so one batch per tile
    const int l0  = m0 & 4095;

    float acc[8][4];
#pragma unroll
    for (int i = 0; i < 8; ++i)
#pragma unroll
        for (int j = 0; j < 4; ++j) acc[i][j] = 0.f;

    for (int k0 = 0; k0 < SDIM; k0 += 16) {
        // A tile: 2048 floats = 512 float4, coalesced along l (m)
#pragma unroll
        for (int r = 0; r < 2; ++r) {
            int lin = tid * 2 + r;          // 0..511
            int k   = lin >> 5;             // 0..15
            int m4  = (lin & 31) << 2;      // 0..124
            float4 v = *reinterpret_cast<const float4*>(
                &x[((size_t)(b * SDIM + k0 + k)) * L_SEQ + l0 + m4]);
            *reinterpret_cast<float4*>(&As[k][m4]) = v;
        }
        // B tile: 1024 floats = 256 float4, coalesced along k
        {
            int n  = tid >> 2;
            int k4 = (tid & 3) << 2;
            float4 v = make_float4(0.f, 0.f, 0.f, 0.f);
            if (n0 + n < P_TOT)
                v = *reinterpret_cast<const float4*>(&Wp[(size_t)(n0 + n) * SDIM + k0 + k4]);
            Bs[k4 + 0][n] = v.x; Bs[k4 + 1][n] = v.y;
            Bs[k4 + 2][n] = v.z; Bs[k4 + 3][n] = v.w;
        }
        __syncthreads();
#pragma unroll
        for (int k = 0; k < 16; ++k) {
            float a[8], bb[4];
#pragma unroll
            for (int i = 0; i < 8; ++i) a[i] = As[k][tx * 8 + i];
#pragma unroll
            for (int j = 0; j < 4; ++j) bb[j] = Bs[k][ty * 4 + j];
#pragma unroll
            for (int i = 0; i < 8; ++i)
#pragma unroll
                for (int j = 0; j < 4; ++j)
                    acc[i][j] = fmaf(a[i], bb[j], acc[i][j]);
        }
        __syncthreads();
    }

    const int ng = n0 + ty * 4;         // 4-aligned; region boundaries (384,768,784,800) 4-aligned
    if (ng >= P_TOT) return;
    float bias[4];
#pragma unroll
    for (int j = 0; j < 4; ++j) bias[j] = bp[ng + j];
    const int m_base = m0 + tx * 8;

    if (ng < SDIM) {                       // x_in
#pragma unroll
        for (int i = 0; i < 8; ++i) {
            float4 v = make_float4(acc[i][0] + bias[0], acc[i][1] + bias[1],
                                   acc[i][2] + bias[2], acc[i][3] + bias[3]);
            *reinterpret_cast<float4*>(&g_xin[(size_t)(m_base + i) * SDIM + ng]) = v;
        }
    } else if (ng < 2 * SDIM) {            // delta -> softplus(delta + dt_bias)
        const int nd = ng - SDIM;
        float db[4];
#pragma unroll
        for (int j = 0; j < 4; ++j) db[j] = dtb[nd + j];
#pragma unroll
        for (int i = 0; i < 8; ++i) {
            float4 v = make_float4(softplusf(acc[i][0] + bias[0] + db[0]),
                                   softplusf(acc[i][1] + bias[1] + db[1]),
                                   softplusf(acc[i][2] + bias[2] + db[2]),
                                   softplusf(acc[i][3] + bias[3] + db[3]));
            *reinterpret_cast<float4*>(&g_dsp[(size_t)(m_base + i) * SDIM + nd]) = v;
        }
    } else if (ng < 2 * SDIM + DST) {      // B matrix
        const int nd = ng - 2 * SDIM;
#pragma unroll
        for (int i = 0; i < 8; ++i) {
            float4 v = make_float4(acc[i][0] + bias[0], acc[i][1] + bias[1],
                                   acc[i][2] + bias[2], acc[i][3] + bias[3]);
            *reinterpret_cast<float4*>(&g_Bm[(size_t)(m_base + i) * DST + nd]) = v;
        }
    } else {                               // C matrix
        const int nd = ng - (2 * SDIM + DST);
#pragma unroll
        for (int i = 0; i < 8; ++i) {
            float4 v = make_float4(acc[i][0] + bias[0], acc[i][1] + bias[1],
                                   acc[i][2] + bias[2], acc[i][3] + bias[3]);
            *reinterpret_cast<float4*>(&g_Cm[(size_t)(m_base + i) * DST + nd]) = v;
        }
    }
}

// ================= selective scan: 1 warp = 2 channels, 16 lanes/channel (lane = state n) =====
__global__ __launch_bounds__(32) void scan_kernel(
    const float* __restrict__ Alog, const float* __restrict__ Dp)
{
    const int lane = threadIdx.x;
    const int ch   = blockIdx.x * 2 + (lane >> 4);   // 0..1535
    const int b    = ch / SDIM;
    const int d    = ch % SDIM;
    const int n    = lane & 15;

    const float A  = -expf(Alog[d * DST + n]);
    const float Dd = Dp[d];
    float h = 0.f;

    size_t ix = (size_t)(b * L_SEQ) * SDIM + d;
    size_t ib = (size_t)(b * L_SEQ) * DST  + n;

    for (int t = 0; t < L_SEQ; ++t) {
        float dt = g_dsp[ix];
        float xv = g_xin[ix];
        float bn = g_Bm[ib];
        float cn = g_Cm[ib];
        float a  = __expf(dt * A);
        h = fmaf(a, h, dt * xv * bn);
        float p = h * cn;
        p += __shfl_xor_sync(0xffffffffu, p, 1);
        p += __shfl_xor_sync(0xffffffffu, p, 2);
        p += __shfl_xor_sync(0xffffffffu, p, 4);
        p += __shfl_xor_sync(0xffffffffu, p, 8);
        if (n == 0) g_y[ix] = fmaf(xv, Dd, p);
        ix += SDIM;
        ib += DST;
    }
}

// ================= out GEMM: (B*L,384) @ (384,384)^T + bias, transposed store ==========
__global__ __launch_bounds__(256) void out_kernel(
    const float* __restrict__ Wo, const float* __restrict__ bo,
    float* __restrict__ out)
{
    __shared__ float As[16][128];
    __shared__ float Bs[16][68];

    const int tid = threadIdx.x;
    const int tx  = tid & 15;
    const int ty  = tid >> 4;
    const int m0  = blockIdx.x * 128;
    const int n0  = blockIdx.y * 64;
    const int b   = m0 >> 12;
    const int l0  = m0 & 4095;

    float acc[8][4];
#pragma unroll
    for (int i = 0; i < 8; ++i)
#pragma unroll
        for (int j = 0; j < 4; ++j) acc[i][j] = 0.f;

    for (int k0 = 0; k0 < SDIM; k0 += 16) {
        // A tile from g_y (k-contiguous): transpose into As[k][m]
#pragma unroll
        for (int r = 0; r < 2; ++r) {
            int lin = tid * 2 + r;       // 0..511
            int m   = lin >> 2;          // 0..127
            int k4  = (lin & 3) << 2;    // 0,4,8,12
            float4 v = *reinterpret_cast<const float4*>(
                &g_y[(size_t)(m0 + m) * SDIM + k0 + k4]);
            As[k4 + 0][m] = v.x; As[k4 + 1][m] = v.y;
            As[k4 + 2][m] = v.z; As[k4 + 3][m] = v.w;
        }
        // B tile from W_out (k-contiguous); N=384 exact, no predication
        {
            int n  = tid >> 2;
            int k4 = (tid & 3) << 2;
            float4 v = *reinterpret_cast<const float4*>(&Wo[(size_t)(n0 + n) * SDIM + k0 + k4]);
            Bs[k4 + 0][n] = v.x; Bs[k4 + 1][n] = v.y;
            Bs[k4 + 2][n] = v.z; Bs[k4 + 3][n] = v.w;
        }
        __syncthreads();
#pragma unroll
        for (int k = 0; k < 16; ++k) {
            float a[8], bb[4];
#pragma unroll
            for (int i = 0; i < 8; ++i) a[i] = As[k][tx * 8 + i];
#pragma unroll
            for (int j = 0; j < 4; ++j) bb[j] = Bs[k][ty * 4 + j];
#pragma unroll
            for (int i = 0; i < 8; ++i)
#pragma unroll
                for (int j = 0; j < 4; ++j)
                    acc[i][j] = fmaf(a[i], bb[j], acc[i][j]);
        }
        __syncthreads();
    }

    // write out[b][n][l] = acc + b_out[n], coalesced along l via float4
#pragma unroll
    for (int j = 0; j < 4; ++j) {
        const int n = n0 + ty * 4 + j;
        const float bj = bo[n];
        float* dst = &out[((size_t)(b * SDIM + n)) * L_SEQ + l0 + tx * 8];
        float4 v0 = make_float4(acc[0][j] + bj, acc[1][j] + bj,
                                acc[2][j] + bj, acc[3][j] + bj);
        float4 v1 = make_float4(acc[4][j] + bj, acc[5][j] + bj,
                                acc[6][j] + bj, acc[7][j] + bj);
        *reinterpret_cast<float4*>(dst)     = v0;
        *reinterpret_cast<float4*>(dst + 4) = v1;
    }
}

extern "C" void kernel_launch(void* const* d_in, const int* in_sizes, int n_in,
                              void* d_out, int out_size)
{
    const float* x    = (const float*)d_in[0];
    const float* Wp   = (const float*)d_in[1];
    const float* bp   = (const float*)d_in[2];
    const float* Alog = (const float*)d_in[3];
    const float* D    = (const float*)d_in[4];
    const float* dtb  = (const float*)d_in[5];
    const float* Wo   = (const float*)d_in[6];
    const float* bo   = (const float*)d_in[7];
    float* out = (float*)d_out;

    dim3 g1(M_TOT / 128, (P_TOT + 63) / 64);   // (128, 13)
    proj_kernel<<<g1, 256>>>(x, Wp, bp, dtb);

    scan_kernel<<<(BATCH * SDIM) / 2, 32>>>(Alog, D);  // 768 warps

    dim3 g2(M_TOT / 128, SDIM / 64);           // (128, 6)
    out_kernel<<<g2, 256>>>(Wo, bo, out);
}

// round 2
// speedup vs baseline: 3.2833x; 3.2833x over previous
#include <cuda_runtime.h>
#include <cstddef>

#define L_SEQ 4096
#define SDIM  384
#define DST   16
#define BATCH 4
#define M_TOT (BATCH * L_SEQ)      // 16384
#define P_TOT (2 * SDIM + 2 * DST) // 800
#define NCH   (BATCH * SDIM)       // 1536 channels
#define T_CHK 128
#define N_CHK (L_SEQ / T_CHK)      // 32
#define CSTATES (NCH * DST)        // 24576 (channel,state) pairs

// ---------------- scratch (no allocations allowed) ----------------
__device__ float g_xin[M_TOT * SDIM];
__device__ float g_dsp[M_TOT * SDIM];
__device__ float g_Bm [M_TOT * DST];
__device__ float g_Cm [M_TOT * DST];
__device__ float g_y  [M_TOT * SDIM];
__device__ float g_aP [N_CHK * CSTATES];
__device__ float g_hP [N_CHK * CSTATES];
__device__ float g_h0 [N_CHK * CSTATES];

__device__ __forceinline__ float softplusf(float z) {
    if (z > 20.f) return z;
    return log1pf(__expf(z));
}

// ================= proj GEMM: (B*L,384) @ (384,800)^T + bias, fused split =================
__global__ __launch_bounds__(256) void proj_kernel(
    const float* __restrict__ x,  const float* __restrict__ Wp,
    const float* __restrict__ bp, const float* __restrict__ dtb)
{
    __shared__ float As[16][128];
    __shared__ float Bs[16][68];

    const int tid = threadIdx.x;
    const int tx  = tid & 15;   // m direction, 8 each
    const int ty  = tid >> 4;   // n direction, 4 each
    const int m0  = blockIdx.x * 128;
    const int n0  = blockIdx.y * 64;
    const int b   = m0 >> 12;
    const int l0  = m0 & 4095;

    float acc[8][4];
#pragma unroll
    for (int i = 0; i < 8; ++i)
#pragma unroll
        for (int j = 0; j < 4; ++j) acc[i][j] = 0.f;

    for (int k0 = 0; k0 < SDIM; k0 += 16) {
#pragma unroll
        for (int r = 0; r < 2; ++r) {
            int lin = tid * 2 + r;
            int k   = lin >> 5;
            int m4  = (lin & 31) << 2;
            float4 v = *reinterpret_cast<const float4*>(
                &x[((size_t)(b * SDIM + k0 + k)) * L_SEQ + l0 + m4]);
            *reinterpret_cast<float4*>(&As[k][m4]) = v;
        }
        {
            int n  = tid >> 2;
            int k4 = (tid & 3) << 2;
            float4 v = make_float4(0.f, 0.f, 0.f, 0.f);
            if (n0 + n < P_TOT)
                v = *reinterpret_cast<const float4*>(&Wp[(size_t)(n0 + n) * SDIM + k0 + k4]);
            Bs[k4 + 0][n] = v.x; Bs[k4 + 1][n] = v.y;
            Bs[k4 + 2][n] = v.z; Bs[k4 + 3][n] = v.w;
        }
        __syncthreads();
#pragma unroll
        for (int k = 0; k < 16; ++k) {
            float a[8], bb[4];
#pragma unroll
            for (int i = 0; i < 8; ++i) a[i] = As[k][tx * 8 + i];
#pragma unroll
            for (int j = 0; j < 4; ++j) bb[j] = Bs[k][ty * 4 + j];
#pragma unroll
            for (int i = 0; i < 8; ++i)
#pragma unroll
                for (int j = 0; j < 4; ++j)
                    acc[i][j] = fmaf(a[i], bb[j], acc[i][j]);
        }
        __syncthreads();
    }

    const int ng = n0 + ty * 4;
    if (ng >= P_TOT) return;
    float bias[4];
#pragma unroll
    for (int j = 0; j < 4; ++j) bias[j] = bp[ng + j];
    const int m_base = m0 + tx * 8;

    if (ng < SDIM) {
#pragma unroll
        for (int i = 0; i < 8; ++i) {
            float4 v = make_float4(acc[i][0] + bias[0], acc[i][1] + bias[1],
                                   acc[i][2] + bias[2], acc[i][3] + bias[3]);
            *reinterpret_cast<float4*>(&g_xin[(size_t)(m_base + i) * SDIM + ng]) = v;
        }
    } else if (ng < 2 * SDIM) {
        const int nd = ng - SDIM;
        float db[4];
#pragma unroll
        for (int j = 0; j < 4; ++j) db[j] = dtb[nd + j];
#pragma unroll
        for (int i = 0; i < 8; ++i) {
            float4 v = make_float4(softplusf(acc[i][0] + bias[0] + db[0]),
                                   softplusf(acc[i][1] + bias[1] + db[1]),
                                   softplusf(acc[i][2] + bias[2] + db[2]),
                                   softplusf(acc[i][3] + bias[3] + db[3]));
            *reinterpret_cast<float4*>(&g_dsp[(size_t)(m_base + i) * SDIM + nd]) = v;
        }
    } else if (ng < 2 * SDIM + DST) {
        const int nd = ng - 2 * SDIM;
#pragma unroll
        for (int i = 0; i < 8; ++i) {
            float4 v = make_float4(acc[i][0] + bias[0], acc[i][1] + bias[1],
                                   acc[i][2] + bias[2], acc[i][3] + bias[3]);
            *reinterpret_cast<float4*>(&g_Bm[(size_t)(m_base + i) * DST + nd]) = v;
        }
    } else {
        const int nd = ng - (2 * SDIM + DST);
#pragma unroll
        for (int i = 0; i < 8; ++i) {
            float4 v = make_float4(acc[i][0] + bias[0], acc[i][1] + bias[1],
                                   acc[i][2] + bias[2], acc[i][3] + bias[3]);
            *reinterpret_cast<float4*>(&g_Cm[(size_t)(m_base + i) * DST + nd]) = v;
        }
    }
}

// ============ Phase A: per-chunk partials (aP = prod a, hP = h from 0) ============
// 1 warp = 2 channels x 1 chunk; lane%16 = state n.
__global__ __launch_bounds__(128) void scanA_kernel(const float* __restrict__ Alog)
{
    const int lane = threadIdx.x & 31;
    const int w    = threadIdx.x >> 5;
    const int ch   = blockIdx.x * 8 + w * 2 + (lane >> 4);
    const int chk  = blockIdx.y;
    const int b    = ch / SDIM;
    const int d    = ch % SDIM;
    const int n    = lane & 15;

    const float A = -expf(Alog[d * DST + n]);
    float aP = 1.f, hP = 0.f;

    const int t0 = chk * T_CHK;
    size_t ix = ((size_t)(b * L_SEQ + t0)) * SDIM + d;
    size_t ib = ((size_t)(b * L_SEQ + t0)) * DST  + n;

#pragma unroll 4
    for (int t = 0; t < T_CHK; ++t) {
        float dt = g_dsp[ix];
        float xv = g_xin[ix];
        float bn = g_Bm[ib];
        float a  = __expf(dt * A);
        hP = fmaf(a, hP, dt * xv * bn);
        aP *= a;
        ix += SDIM;
        ib += DST;
    }
    const int idx = chk * CSTATES + ch * DST + n;
    g_aP[idx] = aP;
    g_hP[idx] = hP;
}

// ============ Phase B: serial combine over 32 chunks -> chunk-start states ============
__global__ __launch_bounds__(256) void scanB_kernel()
{
    const int tid = blockIdx.x * 256 + threadIdx.x;   // 0..CSTATES-1
    float h = 0.f;
#pragma unroll
    for (int c = 0; c < N_CHK; ++c) {
        g_h0[c * CSTATES + tid] = h;
        h = fmaf(g_aP[c * CSTATES + tid], h, g_hP[c * CSTATES + tid]);
    }
}

// ============ Phase C: replay recurrence per chunk with correct h0, emit y ============
__global__ __launch_bounds__(128) void scanC_kernel(
    const float* __restrict__ Alog, const float* __restrict__ Dp)
{
    const int lane = threadIdx.x & 31;
    const int w    = threadIdx.x >> 5;
    const int ch   = blockIdx.x * 8 + w * 2 + (lane >> 4);
    const int chk  = blockIdx.y;
    const int b    = ch / SDIM;
    const int d    = ch % SDIM;
    const int n    = lane & 15;

    const float A  = -expf(Alog[d * DST + n]);
    const float Dd = Dp[d];
    float h = g_h0[chk * CSTATES + ch * DST + n];

    const int t0 = chk * T_CHK;
    size_t ix = ((size_t)(b * L_SEQ + t0)) * SDIM + d;
    size_t ib = ((size_t)(b * L_SEQ + t0)) * DST  + n;

#pragma unroll 4
    for (int t = 0; t < T_CHK; ++t) {
        float dt = g_dsp[ix];
        float xv = g_xin[ix];
        float bn = g_Bm[ib];
        float cn = g_Cm[ib];
        float a  = __expf(dt * A);
        h = fmaf(a, h, dt * xv * bn);
        float p = h * cn;
        p += __shfl_xor_sync(0xffffffffu, p, 1);
        p += __shfl_xor_sync(0xffffffffu, p, 2);
        p += __shfl_xor_sync(0xffffffffu, p, 4);
        p += __shfl_xor_sync(0xffffffffu, p, 8);
        if (n == 0) g_y[ix] = fmaf(xv, Dd, p);
        ix += SDIM;
        ib += DST;
    }
}

// ================= out GEMM: (B*L,384) @ (384,384)^T + bias, transposed store ==========
__global__ __launch_bounds__(256) void out_kernel(
    const float* __restrict__ Wo, const float* __restrict__ bo,
    float* __restrict__ out)
{
    __shared__ float As[16][128];
    __shared__ float Bs[16][68];

    const int tid = threadIdx.x;
    const int tx  = tid & 15;
    const int ty  = tid >> 4;
    const int m0  = blockIdx.x * 128;
    const int n0  = blockIdx.y * 64;
    const int b   = m0 >> 12;
    const int l0  = m0 & 4095;

    float acc[8][4];
#pragma unroll
    for (int i = 0; i < 8; ++i)
#pragma unroll
        for (int j = 0; j < 4; ++j) acc[i][j] = 0.f;

    for (int k0 = 0; k0 < SDIM; k0 += 16) {
#pragma unroll
        for (int r = 0; r < 2; ++r) {
            int lin = tid * 2 + r;
            int m   = lin >> 2;
            int k4  = (lin & 3) << 2;
            float4 v = *reinterpret_cast<const float4*>(
                &g_y[(size_t)(m0 + m) * SDIM + k0 + k4]);
            As[k4 + 0][m] = v.x; As[k4 + 1][m] = v.y;
            As[k4 + 2][m] = v.z; As[k4 + 3][m] = v.w;
        }
        {
            int n  = tid >> 2;
            int k4 = (tid & 3) << 2;
            float4 v = *reinterpret_cast<const float4*>(&Wo[(size_t)(n0 + n) * SDIM + k0 + k4]);
            Bs[k4 + 0][n] = v.x; Bs[k4 + 1][n] = v.y;
            Bs[k4 + 2][n] = v.z; Bs[k4 + 3][n] = v.w;
        }
        __syncthreads();
#pragma unroll
        for (int k = 0; k < 16; ++k) {
            float a[8], bb[4];
#pragma unroll
            for (int i = 0; i < 8; ++i) a[i] = As[k][tx * 8 + i];
#pragma unroll
            for (int j = 0; j < 4; ++j) bb[j] = Bs[k][ty * 4 + j];
#pragma unroll
            for (int i = 0; i < 8; ++i)
#pragma unroll
                for (int j = 0; j < 4; ++j)
                    acc[i][j] = fmaf(a[i], bb[j], acc[i][j]);
        }
        __syncthreads();
    }

#pragma unroll
    for (int j = 0; j < 4; ++j) {
        const int n = n0 + ty * 4 + j;
        const float bj = bo[n];
        float* dst = &out[((size_t)(b * SDIM + n)) * L_SEQ + l0 + tx * 8];
        float4 v0 = make_float4(acc[0][j] + bj, acc[1][j] + bj,
                                acc[2][j] + bj, acc[3][j] + bj);
        float4 v1 = make_float4(acc[4][j] + bj, acc[5][j] + bj,
                                acc[6][j] + bj, acc[7][j] + bj);
        *reinterpret_cast<float4*>(dst)     = v0;
        *reinterpret_cast<float4*>(dst + 4) = v1;
    }
}

extern "C" void kernel_launch(void* const* d_in, const int* in_sizes, int n_in,
                              void* d_out, int out_size)
{
    const float* x    = (const float*)d_in[0];
    const float* Wp   = (const float*)d_in[1];
    const float* bp   = (const float*)d_in[2];
    const float* Alog = (const float*)d_in[3];
    const float* D    = (const float*)d_in[4];
    const float* dtb  = (const float*)d_in[5];
    const float* Wo   = (const float*)d_in[6];
    const float* bo   = (const float*)d_in[7];
    float* out = (float*)d_out;

    dim3 g1(M_TOT / 128, (P_TOT + 63) / 64);   // (128, 13)
    proj_kernel<<<g1, 256>>>(x, Wp, bp, dtb);

    dim3 gs(NCH / 8, N_CHK);                   // (192, 32)
    scanA_kernel<<<gs, 128>>>(Alog);
    scanB_kernel<<<CSTATES / 256, 256>>>();    // 96 blocks
    scanC_kernel<<<gs, 128>>>(Alog, D);

    dim3 g2(M_TOT / 128, SDIM / 64);           // (128, 6)
    out_kernel<<<g2, 256>>>(Wo, bo, out);
}

// round 3
// speedup vs baseline: 5.1911x; 1.5811x over previous
#include <cuda_runtime.h>
#include <cstddef>

#define L_SEQ 4096
#define SDIM  384
#define DST   16
#define BATCH 4
#define M_TOT (BATCH * L_SEQ)      // 16384
#define P_TOT (2 * SDIM + 2 * DST) // 800
#define NCH   (BATCH * SDIM)       // 1536 channels
#define T_CHK 128
#define N_CHK (L_SEQ / T_CHK)      // 32
#define CSTATES (NCH * DST)        // 24576

// ---------------- scratch ----------------
__device__ float g_xin[M_TOT * SDIM];
__device__ float g_dsp[M_TOT * SDIM];
__device__ float g_Bm [M_TOT * DST];
__device__ float g_Cm [M_TOT * DST];
__device__ float g_y  [M_TOT * SDIM];
__device__ float g_aP [N_CHK * CSTATES];
__device__ float g_hP [N_CHK * CSTATES];
__device__ float g_h0 [N_CHK * CSTATES];

__device__ __forceinline__ float softplusf(float z) {
    if (z > 20.f) return z;
    return log1pf(__expf(z));
}

// =========================================================================
// proj GEMM: (16384,384) @ (384,800)^T + bias, fused region split
// BM=BN=128, BK=16, 256 threads, 8x8 micro, double-buffered smem
// =========================================================================
#define SSTR 132   // padded smem row stride (floats)

__global__ __launch_bounds__(256) void proj_kernel(
    const float* __restrict__ x,  const float* __restrict__ Wp,
    const float* __restrict__ bp, const float* __restrict__ dtb)
{
    __shared__ float As[2][16 * SSTR];
    __shared__ float Bs[2][16 * SSTR];

    const int tid = threadIdx.x;
    const int tx  = tid & 15;    // n dir
    const int ty  = tid >> 4;    // m dir
    const int m0  = blockIdx.x * 128;
    const int n0  = blockIdx.y * 128;
    const int b   = m0 >> 12;
    const int l0  = m0 & 4095;

    // A-load mapping: f4 index q = tid + r*256, k=q>>5, m4=(q&31)*4
    // B-load mapping: q = tid + r*256, n=q>>2, k4=(q&3)*4
    float4 Ar[2], Br[2];
    const bool bn_ok[2] = { (n0 + (tid >> 2))       < P_TOT,
                            (n0 + ((tid + 256) >> 2)) < P_TOT };

    auto ldgA = [&](int k0) {
#pragma unroll
        for (int r = 0; r < 2; ++r) {
            int q = tid + r * 256;
            int k = q >> 5, m4 = (q & 31) << 2;
            Ar[r] = *reinterpret_cast<const float4*>(
                &x[((size_t)(b * SDIM + k0 + k)) * L_SEQ + l0 + m4]);
        }
    };
    auto ldgB = [&](int k0) {
#pragma unroll
        for (int r = 0; r < 2; ++r) {
            int q = tid + r * 256;
            int n = q >> 2, k4 = (q & 3) << 2;
            Br[r] = bn_ok[r]
                ? *reinterpret_cast<const float4*>(&Wp[(size_t)(n0 + n) * SDIM + k0 + k4])
                : make_float4(0.f, 0.f, 0.f, 0.f);
        }
    };
    auto sts = [&](int buf) {
#pragma unroll
        for (int r = 0; r < 2; ++r) {
            int q = tid + r * 256;
            int k = q >> 5, m4 = (q & 31) << 2;
            *reinterpret_cast<float4*>(&As[buf][k * SSTR + m4]) = Ar[r];
            int n = q >> 2, k4 = (q & 3) << 2;
            Bs[buf][(k4 + 0) * SSTR + n] = Br[r].x;
            Bs[buf][(k4 + 1) * SSTR + n] = Br[r].y;
            Bs[buf][(k4 + 2) * SSTR + n] = Br[r].z;
            Bs[buf][(k4 + 3) * SSTR + n] = Br[r].w;
        }
    };

    float acc[8][8];
#pragma unroll
    for (int i = 0; i < 8; ++i)
#pragma unroll
        for (int j = 0; j < 8; ++j) acc[i][j] = 0.f;

    ldgA(0); ldgB(0);
    sts(0);
    __syncthreads();

    const int KT = SDIM / 16;  // 24
    for (int kt = 0; kt < KT; ++kt) {
        int cur = kt & 1;
        if (kt + 1 < KT) { ldgA((kt + 1) * 16); ldgB((kt + 1) * 16); }
#pragma unroll
        for (int k = 0; k < 16; ++k) {
            float a[8], bb[8];
            float4 a0 = *reinterpret_cast<const float4*>(&As[cur][k * SSTR + ty * 8]);
            float4 a1 = *reinterpret_cast<const float4*>(&As[cur][k * SSTR + ty * 8 + 4]);
            float4 b0 = *reinterpret_cast<const float4*>(&Bs[cur][k * SSTR + tx * 8]);
            float4 b1 = *reinterpret_cast<const float4*>(&Bs[cur][k * SSTR + tx * 8 + 4]);
            a[0]=a0.x;a[1]=a0.y;a[2]=a0.z;a[3]=a0.w;a[4]=a1.x;a[5]=a1.y;a[6]=a1.z;a[7]=a1.w;
            bb[0]=b0.x;bb[1]=b0.y;bb[2]=b0.z;bb[3]=b0.w;bb[4]=b1.x;bb[5]=b1.y;bb[6]=b1.z;bb[7]=b1.w;
#pragma unroll
            for (int i = 0; i < 8; ++i)
#pragma unroll
                for (int j = 0; j < 8; ++j)
                    acc[i][j] = fmaf(a[i], bb[j], acc[i][j]);
        }
        if (kt + 1 < KT) {
            sts(cur ^ 1);
            __syncthreads();
        }
    }

    // epilogue: per-thread 8 cols all in ONE region (boundaries 384/768/784/800 are 8-aligned)
    const int nbase = n0 + tx * 8;
    if (nbase >= P_TOT) return;
    float bias[8];
#pragma unroll
    for (int j = 0; j < 8; ++j) bias[j] = bp[nbase + j];
    const int mb = m0 + ty * 8;

    if (nbase < SDIM) {
#pragma unroll
        for (int i = 0; i < 8; ++i) {
            float* dst = &g_xin[(size_t)(mb + i) * SDIM + nbase];
            float4 v0 = make_float4(acc[i][0]+bias[0], acc[i][1]+bias[1], acc[i][2]+bias[2], acc[i][3]+bias[3]);
            float4 v1 = make_float4(acc[i][4]+bias[4], acc[i][5]+bias[5], acc[i][6]+bias[6], acc[i][7]+bias[7]);
            *reinterpret_cast<float4*>(dst)     = v0;
            *reinterpret_cast<float4*>(dst + 4) = v1;
        }
    } else if (nbase < 2 * SDIM) {
        const int nd = nbase - SDIM;
        float db[8];
#pragma unroll
        for (int j = 0; j < 8; ++j) db[j] = dtb[nd + j];
#pragma unroll
        for (int i = 0; i < 8; ++i) {
            float* dst = &g_dsp[(size_t)(mb + i) * SDIM + nd];
            float4 v0 = make_float4(softplusf(acc[i][0]+bias[0]+db[0]), softplusf(acc[i][1]+bias[1]+db[1]),
                                    softplusf(acc[i][2]+bias[2]+db[2]), softplusf(acc[i][3]+bias[3]+db[3]));
            float4 v1 = make_float4(softplusf(acc[i][4]+bias[4]+db[4]), softplusf(acc[i][5]+bias[5]+db[5]),
                                    softplusf(acc[i][6]+bias[6]+db[6]), softplusf(acc[i][7]+bias[7]+db[7]));
            *reinterpret_cast<float4*>(dst)     = v0;
            *reinterpret_cast<float4*>(dst + 4) = v1;
        }
    } else if (nbase < 2 * SDIM + DST) {
        const int nd = nbase - 2 * SDIM;
#pragma unroll
        for (int i = 0; i < 8; ++i) {
            float* dst = &g_Bm[(size_t)(mb + i) * DST + nd];
            float4 v0 = make_float4(acc[i][0]+bias[0], acc[i][1]+bias[1], acc[i][2]+bias[2], acc[i][3]+bias[3]);
            float4 v1 = make_float4(acc[i][4]+bias[4], acc[i][5]+bias[5], acc[i][6]+bias[6], acc[i][7]+bias[7]);
            *reinterpret_cast<float4*>(dst)     = v0;
            *reinterpret_cast<float4*>(dst + 4) = v1;
        }
    } else {
        const int nd = nbase - (2 * SDIM + DST);
#pragma unroll
        for (int i = 0; i < 8; ++i) {
            float* dst = &g_Cm[(size_t)(mb + i) * DST + nd];
            float4 v0 = make_float4(acc[i][0]+bias[0], acc[i][1]+bias[1], acc[i][2]+bias[2], acc[i][3]+bias[3]);
            float4 v1 = make_float4(acc[i][4]+bias[4], acc[i][5]+bias[5], acc[i][6]+bias[6], acc[i][7]+bias[7]);
            *reinterpret_cast<float4*>(dst)     = v0;
            *reinterpret_cast<float4*>(dst + 4) = v1;
        }
    }
}

// =========================================================================
// Scan: thread-per-channel, 16 states in registers, B/C staged in smem
// grid (SDIM/128, BATCH, N_CHK), 128 threads
// =========================================================================
__global__ __launch_bounds__(128) void scanA_kernel(const float* __restrict__ Alog)
{
    __shared__ float Bsh[T_CHK * DST];   // 8KB

    const int tid = threadIdx.x;
    const int d   = blockIdx.x * 128 + tid;
    const int b   = blockIdx.y;
    const int chk = blockIdx.z;
    const int t0  = chk * T_CHK;
    const int ch  = b * SDIM + d;

    {   // stage B chunk: 2048 floats, coalesced
        const float4* src = reinterpret_cast<const float4*>(&g_Bm[((size_t)(b * L_SEQ + t0)) * DST]);
        float4* dst = reinterpret_cast<float4*>(Bsh);
#pragma unroll
        for (int j = 0; j < 4; ++j) dst[tid + j * 128] = src[tid + j * 128];
    }

    float A[DST], h[DST], aP[DST];
#pragma unroll
    for (int n = 0; n < DST; ++n) {
        A[n] = -expf(Alog[d * DST + n]);
        h[n] = 0.f; aP[n] = 1.f;
    }
    __syncthreads();

    size_t ix = ((size_t)(b * L_SEQ + t0)) * SDIM + d;
    for (int t = 0; t < T_CHK; ++t) {
        float dt = g_dsp[ix];
        float xv = g_xin[ix];
        float u  = dt * xv;
        const float4* Bq = reinterpret_cast<const float4*>(&Bsh[t * DST]);
#pragma unroll
        for (int j = 0; j < 4; ++j) {
            float4 bv = Bq[j];
            float e0 = __expf(dt * A[j*4+0]);
            float e1 = __expf(dt * A[j*4+1]);
            float e2 = __expf(dt * A[j*4+2]);
            float e3 = __expf(dt * A[j*4+3]);
            h[j*4+0] = fmaf(e0, h[j*4+0], u * bv.x); aP[j*4+0] *= e0;
            h[j*4+1] = fmaf(e1, h[j*4+1], u * bv.y); aP[j*4+1] *= e1;
            h[j*4+2] = fmaf(e2, h[j*4+2], u * bv.z); aP[j*4+2] *= e2;
            h[j*4+3] = fmaf(e3, h[j*4+3], u * bv.w); aP[j*4+3] *= e3;
        }
        ix += SDIM;
    }

    const size_t ob = (size_t)chk * CSTATES + (size_t)ch * DST;
#pragma unroll
    for (int j = 0; j < 4; ++j) {
        *reinterpret_cast<float4*>(&g_aP[ob + j*4]) = make_float4(aP[j*4], aP[j*4+1], aP[j*4+2], aP[j*4+3]);
        *reinterpret_cast<float4*>(&g_hP[ob + j*4]) = make_float4(h [j*4], h [j*4+1], h [j*4+2], h [j*4+3]);
    }
}

__global__ __launch_bounds__(256) void scanB_kernel()
{
    const int tid = blockIdx.x * 256 + threadIdx.x;   // 0..CSTATES-1
    float h = 0.f;
#pragma unroll
    for (int c = 0; c < N_CHK; ++c) {
        g_h0[c * CSTATES + tid] = h;
        h = fmaf(g_aP[c * CSTATES + tid], h, g_hP[c * CSTATES + tid]);
    }
}

__global__ __launch_bounds__(128) void scanC_kernel(
    const float* __restrict__ Alog, const float* __restrict__ Dp)
{
    __shared__ float Bsh[T_CHK * DST];
    __shared__ float Csh[T_CHK * DST];

    const int tid = threadIdx.x;
    const int d   = blockIdx.x * 128 + tid;
    const int b   = blockIdx.y;
    const int chk = blockIdx.z;
    const int t0  = chk * T_CHK;
    const int ch  = b * SDIM + d;

    {
        const float4* srcB = reinterpret_cast<const float4*>(&g_Bm[((size_t)(b * L_SEQ + t0)) * DST]);
        const float4* srcC = reinterpret_cast<const float4*>(&g_Cm[((size_t)(b * L_SEQ + t0)) * DST]);
        float4* dB = reinterpret_cast<float4*>(Bsh);
        float4* dC = reinterpret_cast<float4*>(Csh);
#pragma unroll
        for (int j = 0; j < 4; ++j) { dB[tid + j * 128] = srcB[tid + j * 128];
                                      dC[tid + j * 128] = srcC[tid + j * 128]; }
    }

    float A[DST], h[DST];
#pragma unroll
    for (int n = 0; n < DST; ++n)
        A[n] = -expf(Alog[d * DST + n]);
    {
        const size_t hb = (size_t)chk * CSTATES + (size_t)ch * DST;
#pragma unroll
        for (int j = 0; j < 4; ++j) {
            float4 v = *reinterpret_cast<const float4*>(&g_h0[hb + j*4]);
            h[j*4+0] = v.x; h[j*4+1] = v.y; h[j*4+2] = v.z; h[j*4+3] = v.w;
        }
    }
    const float Dd = Dp[d];
    __syncthreads();

    size_t ix = ((size_t)(b * L_SEQ + t0)) * SDIM + d;
    for (int t = 0; t < T_CHK; ++t) {
        float dt = g_dsp[ix];
        float xv = g_xin[ix];
        float u  = dt * xv;
        float p  = xv * Dd;
        const float4* Bq = reinterpret_cast<const float4*>(&Bsh[t * DST]);
        const float4* Cq = reinterpret_cast<const float4*>(&Csh[t * DST]);
#pragma unroll
        for (int j = 0; j < 4; ++j) {
            float4 bv = Bq[j];
            float4 cv = Cq[j];
            float e0 = __expf(dt * A[j*4+0]);
            float e1 = __expf(dt * A[j*4+1]);
            float e2 = __expf(dt * A[j*4+2]);
            float e3 = __expf(dt * A[j*4+3]);
            h[j*4+0] = fmaf(e0, h[j*4+0], u * bv.x);
            h[j*4+1] = fmaf(e1, h[j*4+1], u * bv.y);
            h[j*4+2] = fmaf(e2, h[j*4+2], u * bv.z);
            h[j*4+3] = fmaf(e3, h[j*4+3], u * bv.w);
            p = fmaf(h[j*4+0], cv.x, p);
            p = fmaf(h[j*4+1], cv.y, p);
            p = fmaf(h[j*4+2], cv.z, p);
            p = fmaf(h[j*4+3], cv.w, p);
        }
        g_y[ix] = p;
        ix += SDIM;
    }
}

// =========================================================================
// out GEMM: (16384,384) @ (384,384)^T + bias, transposed coalesced store
// =========================================================================
__global__ __launch_bounds__(256) void out_kernel(
    const float* __restrict__ Wo, const float* __restrict__ bo,
    float* __restrict__ out)
{
    __shared__ float As[2][16 * SSTR];
    __shared__ float Bs[2][16 * SSTR];

    const int tid = threadIdx.x;
    const int tx  = tid & 15;
    const int ty  = tid >> 4;
    const int m0  = blockIdx.x * 128;
    const int n0  = blockIdx.y * 128;
    const int b   = m0 >> 12;
    const int l0  = m0 & 4095;

    float4 Ar[2], Br[2];
    auto ldg = [&](int k0) {
#pragma unroll
        for (int r = 0; r < 2; ++r) {
            int q = tid + r * 256;
            int m = q >> 2, k4 = (q & 3) << 2;
            Ar[r] = *reinterpret_cast<const float4*>(&g_y[(size_t)(m0 + m) * SDIM + k0 + k4]);
            int n = q >> 2;
            Br[r] = *reinterpret_cast<const float4*>(&Wo[(size_t)(n0 + n) * SDIM + k0 + k4]);
        }
    };
    auto sts = [&](int buf) {
#pragma unroll
        for (int r = 0; r < 2; ++r) {
            int q = tid + r * 256;
            int m = q >> 2, k4 = (q & 3) << 2;
            As[buf][(k4 + 0) * SSTR + m] = Ar[r].x;
            As[buf][(k4 + 1) * SSTR + m] = Ar[r].y;
            As[buf][(k4 + 2) * SSTR + m] = Ar[r].z;
            As[buf][(k4 + 3) * SSTR + m] = Ar[r].w;
            Bs[buf][(k4 + 0) * SSTR + m] = Br[r].x;
            Bs[buf][(k4 + 1) * SSTR + m] = Br[r].y;
            Bs[buf][(k4 + 2) * SSTR + m] = Br[r].z;
            Bs[buf][(k4 + 3) * SSTR + m] = Br[r].w;
        }
    };

    float acc[8][8];
#pragma unroll
    for (int i = 0; i < 8; ++i)
#pragma unroll
        for (int j = 0; j < 8; ++j) acc[i][j] = 0.f;

    ldg(0);
    sts(0);
    __syncthreads();

    const int KT = SDIM / 16;
    for (int kt = 0; kt < KT; ++kt) {
        int cur = kt & 1;
        if (kt + 1 < KT) ldg((kt + 1) * 16);
#pragma unroll
        for (int k = 0; k < 16; ++k) {
            float a[8], bb[8];
            float4 a0 = *reinterpret_cast<const float4*>(&As[cur][k * SSTR + ty * 8]);
            float4 a1 = *reinterpret_cast<const float4*>(&As[cur][k * SSTR + ty * 8 + 4]);
            float4 b0 = *reinterpret_cast<const float4*>(&Bs[cur][k * SSTR + tx * 8]);
            float4 b1 = *reinterpret_cast<const float4*>(&Bs[cur][k * SSTR + tx * 8 + 4]);
            a[0]=a0.x;a[1]=a0.y;a[2]=a0.z;a[3]=a0.w;a[4]=a1.x;a[5]=a1.y;a[6]=a1.z;a[7]=a1.w;
            bb[0]=b0.x;bb[1]=b0.y;bb[2]=b0.z;bb[3]=b0.w;bb[4]=b1.x;bb[5]=b1.y;bb[6]=b1.z;bb[7]=b1.w;
#pragma unroll
            for (int i = 0; i < 8; ++i)
#pragma unroll
                for (int j = 0; j < 8; ++j)
                    acc[i][j] = fmaf(a[i], bb[j], acc[i][j]);
        }
        if (kt + 1 < KT) {
            sts(cur ^ 1);
            __syncthreads();
        }
    }

    // out[b][n][l], coalesced along l (= m dir, ty*8 rows per thread)
#pragma unroll
    for (int j = 0; j < 8; ++j) {
        const int n = n0 + tx * 8 + j;
        const float bj = bo[n];
        float* dst = &out[((size_t)(b * SDIM + n)) * L_SEQ + l0 + ty * 8];
        float4 v0 = make_float4(acc[0][j]+bj, acc[1][j]+bj, acc[2][j]+bj, acc[3][j]+bj);
        float4 v1 = make_float4(acc[4][j]+bj, acc[5][j]+bj, acc[6][j]+bj, acc[7][j]+bj);
        *reinterpret_cast<float4*>(dst)     = v0;
        *reinterpret_cast<float4*>(dst + 4) = v1;
    }
}

extern "C" void kernel_launch(void* const* d_in, const int* in_sizes, int n_in,
                              void* d_out, int out_size)
{
    const float* x    = (const float*)d_in[0];
    const float* Wp   = (const float*)d_in[1];
    const float* bp   = (const float*)d_in[2];
    const float* Alog = (const float*)d_in[3];
    const float* D    = (const float*)d_in[4];
    const float* dtb  = (const float*)d_in[5];
    const float* Wo   = (const float*)d_in[6];
    const float* bo   = (const float*)d_in[7];
    float* out = (float*)d_out;

    dim3 g1(M_TOT / 128, (P_TOT + 127) / 128);   // (128, 7)
    proj_kernel<<<g1, 256>>>(x, Wp, bp, dtb);

    dim3 gs(SDIM / 128, BATCH, N_CHK);           // (3, 4, 32)
    scanA_kernel<<<gs, 128>>>(Alog);
    scanB_kernel<<<CSTATES / 256, 256>>>();
    scanC_kernel<<<gs, 128>>>(Alog, D);

    dim3 g2(M_TOT / 128, SDIM / 128);            // (128, 3)
    out_kernel<<<g2, 256>>>(Wo, bo, out);
}

// round 4
// speedup vs baseline: 5.7283x; 1.1035x over previous
#include <cuda_runtime.h>
#include <cstddef>

#define L_SEQ 4096
#define SDIM  384
#define DST   16
#define BATCH 4
#define M_TOT (BATCH * L_SEQ)      // 16384
#define P_TOT (2 * SDIM + 2 * DST) // 800
#define NCH   (BATCH * SDIM)       // 1536 channels
#define T_CHK 32
#define N_CHK (L_SEQ / T_CHK)      // 128
#define CSTATES (NCH * DST)        // 24576

// ---------------- scratch ----------------
__device__ float g_xin[M_TOT * SDIM];
__device__ float g_dsp[M_TOT * SDIM];
__device__ float g_Bm [M_TOT * DST];
__device__ float g_Cm [M_TOT * DST];
__device__ float g_y  [M_TOT * SDIM];
__device__ float g_aP [N_CHK * CSTATES];
__device__ float g_hP [N_CHK * CSTATES];
__device__ float g_h0 [N_CHK * CSTATES];

__device__ __forceinline__ float softplusf(float z) {
    if (z > 20.f) return z;
    return log1pf(__expf(z));
}

// =========================================================================
// proj GEMM: (16384,384) @ (384,800)^T + bias, fused region split
// BM=BN=128, BK=16, 256 threads, 8x8 micro, double-buffered smem
// =========================================================================
#define SSTR 132   // padded smem row stride (floats)

__global__ __launch_bounds__(256) void proj_kernel(
    const float* __restrict__ x,  const float* __restrict__ Wp,
    const float* __restrict__ bp, const float* __restrict__ dtb)
{
    __shared__ float As[2][16 * SSTR];
    __shared__ float Bs[2][16 * SSTR];

    const int tid = threadIdx.x;
    const int tx  = tid & 15;    // n dir
    const int ty  = tid >> 4;    // m dir
    const int m0  = blockIdx.x * 128;
    const int n0  = blockIdx.y * 128;
    const int b   = m0 >> 12;
    const int l0  = m0 & 4095;

    float4 Ar[2], Br[2];
    const bool bn_ok[2] = { (n0 + (tid >> 2))       < P_TOT,
                            (n0 + ((tid + 256) >> 2)) < P_TOT };

    auto ldgA = [&](int k0) {
#pragma unroll
        for (int r = 0; r < 2; ++r) {
            int q = tid + r * 256;
            int k = q >> 5, m4 = (q & 31) << 2;
            Ar[r] = *reinterpret_cast<const float4*>(
                &x[((size_t)(b * SDIM + k0 + k)) * L_SEQ + l0 + m4]);
        }
    };
    auto ldgB = [&](int k0) {
#pragma unroll
        for (int r = 0; r < 2; ++r) {
            int q = tid + r * 256;
            int n = q >> 2, k4 = (q & 3) << 2;
            Br[r] = bn_ok[r]
                ? *reinterpret_cast<const float4*>(&Wp[(size_t)(n0 + n) * SDIM + k0 + k4])
                : make_float4(0.f, 0.f, 0.f, 0.f);
        }
    };
    auto sts = [&](int buf) {
#pragma unroll
        for (int r = 0; r < 2; ++r) {
            int q = tid + r * 256;
            int k = q >> 5, m4 = (q & 31) << 2;
            *reinterpret_cast<float4*>(&As[buf][k * SSTR + m4]) = Ar[r];
            int n = q >> 2, k4 = (q & 3) << 2;
            Bs[buf][(k4 + 0) * SSTR + n] = Br[r].x;
            Bs[buf][(k4 + 1) * SSTR + n] = Br[r].y;
            Bs[buf][(k4 + 2) * SSTR + n] = Br[r].z;
            Bs[buf][(k4 + 3) * SSTR + n] = Br[r].w;
        }
    };

    float acc[8][8];
#pragma unroll
    for (int i = 0; i < 8; ++i)
#pragma unroll
        for (int j = 0; j < 8; ++j) acc[i][j] = 0.f;

    ldgA(0); ldgB(0);
    sts(0);
    __syncthreads();

    const int KT = SDIM / 16;  // 24
    for (int kt = 0; kt < KT; ++kt) {
        int cur = kt & 1;
        if (kt + 1 < KT) { ldgA((kt + 1) * 16); ldgB((kt + 1) * 16); }
#pragma unroll
        for (int k = 0; k < 16; ++k) {
            float a[8], bb[8];
            float4 a0 = *reinterpret_cast<const float4*>(&As[cur][k * SSTR + ty * 8]);
            float4 a1 = *reinterpret_cast<const float4*>(&As[cur][k * SSTR + ty * 8 + 4]);
            float4 b0 = *reinterpret_cast<const float4*>(&Bs[cur][k * SSTR + tx * 8]);
            float4 b1 = *reinterpret_cast<const float4*>(&Bs[cur][k * SSTR + tx * 8 + 4]);
            a[0]=a0.x;a[1]=a0.y;a[2]=a0.z;a[3]=a0.w;a[4]=a1.x;a[5]=a1.y;a[6]=a1.z;a[7]=a1.w;
            bb[0]=b0.x;bb[1]=b0.y;bb[2]=b0.z;bb[3]=b0.w;bb[4]=b1.x;bb[5]=b1.y;bb[6]=b1.z;bb[7]=b1.w;
#pragma unroll
            for (int i = 0; i < 8; ++i)
#pragma unroll
                for (int j = 0; j < 8; ++j)
                    acc[i][j] = fmaf(a[i], bb[j], acc[i][j]);
        }
        if (kt + 1 < KT) {
            sts(cur ^ 1);
            __syncthreads();
        }
    }

    const int nbase = n0 + tx * 8;
    if (nbase >= P_TOT) return;
    float bias[8];
#pragma unroll
    for (int j = 0; j < 8; ++j) bias[j] = bp[nbase + j];
    const int mb = m0 + ty * 8;

    if (nbase < SDIM) {
#pragma unroll
        for (int i = 0; i < 8; ++i) {
            float* dst = &g_xin[(size_t)(mb + i) * SDIM + nbase];
            float4 v0 = make_float4(acc[i][0]+bias[0], acc[i][1]+bias[1], acc[i][2]+bias[2], acc[i][3]+bias[3]);
            float4 v1 = make_float4(acc[i][4]+bias[4], acc[i][5]+bias[5], acc[i][6]+bias[6], acc[i][7]+bias[7]);
            *reinterpret_cast<float4*>(dst)     = v0;
            *reinterpret_cast<float4*>(dst + 4) = v1;
        }
    } else if (nbase < 2 * SDIM) {
        const int nd = nbase - SDIM;
        float db[8];
#pragma unroll
        for (int j = 0; j < 8; ++j) db[j] = dtb[nd + j];
#pragma unroll
        for (int i = 0; i < 8; ++i) {
            float* dst = &g_dsp[(size_t)(mb + i) * SDIM + nd];
            float4 v0 = make_float4(softplusf(acc[i][0]+bias[0]+db[0]), softplusf(acc[i][1]+bias[1]+db[1]),
                                    softplusf(acc[i][2]+bias[2]+db[2]), softplusf(acc[i][3]+bias[3]+db[3]));
            float4 v1 = make_float4(softplusf(acc[i][4]+bias[4]+db[4]), softplusf(acc[i][5]+bias[5]+db[5]),
                                    softplusf(acc[i][6]+bias[6]+db[6]), softplusf(acc[i][7]+bias[7]+db[7]));
            *reinterpret_cast<float4*>(dst)     = v0;
            *reinterpret_cast<float4*>(dst + 4) = v1;
        }
    } else if (nbase < 2 * SDIM + DST) {
        const int nd = nbase - 2 * SDIM;
#pragma unroll
        for (int i = 0; i < 8; ++i) {
            float* dst = &g_Bm[(size_t)(mb + i) * DST + nd];
            float4 v0 = make_float4(acc[i][0]+bias[0], acc[i][1]+bias[1], acc[i][2]+bias[2], acc[i][3]+bias[3]);
            float4 v1 = make_float4(acc[i][4]+bias[4], acc[i][5]+bias[5], acc[i][6]+bias[6], acc[i][7]+bias[7]);
            *reinterpret_cast<float4*>(dst)     = v0;
            *reinterpret_cast<float4*>(dst + 4) = v1;
        }
    } else {
        const int nd = nbase - (2 * SDIM + DST);
#pragma unroll
        for (int i = 0; i < 8; ++i) {
            float* dst = &g_Cm[(size_t)(mb + i) * DST + nd];
            float4 v0 = make_float4(acc[i][0]+bias[0], acc[i][1]+bias[1], acc[i][2]+bias[2], acc[i][3]+bias[3]);
            float4 v1 = make_float4(acc[i][4]+bias[4], acc[i][5]+bias[5], acc[i][6]+bias[6], acc[i][7]+bias[7]);
            *reinterpret_cast<float4*>(dst)     = v0;
            *reinterpret_cast<float4*>(dst + 4) = v1;
        }
    }
}

// =========================================================================
// Scan: thread-per-channel, 16 states in registers, B/C staged in smem
// grid (SDIM/128, BATCH, N_CHK), 128 threads; T_CHK=32 for occupancy
// =========================================================================
__global__ __launch_bounds__(128) void scanA_kernel(const float* __restrict__ Alog)
{
    __shared__ float Bsh[T_CHK * DST];   // 2KB

    const int tid = threadIdx.x;
    const int d   = blockIdx.x * 128 + tid;
    const int b   = blockIdx.y;
    const int chk = blockIdx.z;
    const int t0  = chk * T_CHK;
    const int ch  = b * SDIM + d;

    {   // stage B chunk: 512 floats = 128 float4, coalesced
        const float4* src = reinterpret_cast<const float4*>(&g_Bm[((size_t)(b * L_SEQ + t0)) * DST]);
        reinterpret_cast<float4*>(Bsh)[tid] = __ldg(&src[tid]);
    }

    float A[DST], h[DST], aP[DST];
#pragma unroll
    for (int n = 0; n < DST; ++n) {
        A[n] = -expf(__ldg(&Alog[d * DST + n]));
        h[n] = 0.f; aP[n] = 1.f;
    }
    __syncthreads();

    size_t ix = ((size_t)(b * L_SEQ + t0)) * SDIM + d;
#pragma unroll 4
    for (int t = 0; t < T_CHK; ++t) {
        float dt = __ldg(&g_dsp[ix]);
        float xv = __ldg(&g_xin[ix]);
        float u  = dt * xv;
        const float4* Bq = reinterpret_cast<const float4*>(&Bsh[t * DST]);
#pragma unroll
        for (int j = 0; j < 4; ++j) {
            float4 bv = Bq[j];
            float e0 = __expf(dt * A[j*4+0]);
            float e1 = __expf(dt * A[j*4+1]);
            float e2 = __expf(dt * A[j*4+2]);
            float e3 = __expf(dt * A[j*4+3]);
            h[j*4+0] = fmaf(e0, h[j*4+0], u * bv.x); aP[j*4+0] *= e0;
            h[j*4+1] = fmaf(e1, h[j*4+1], u * bv.y); aP[j*4+1] *= e1;
            h[j*4+2] = fmaf(e2, h[j*4+2], u * bv.z); aP[j*4+2] *= e2;
            h[j*4+3] = fmaf(e3, h[j*4+3], u * bv.w); aP[j*4+3] *= e3;
        }
        ix += SDIM;
    }

    const size_t ob = (size_t)chk * CSTATES + (size_t)ch * DST;
#pragma unroll
    for (int j = 0; j < 4; ++j) {
        *reinterpret_cast<float4*>(&g_aP[ob + j*4]) = make_float4(aP[j*4], aP[j*4+1], aP[j*4+2], aP[j*4+3]);
        *reinterpret_cast<float4*>(&g_hP[ob + j*4]) = make_float4(h [j*4], h [j*4+1], h [j*4+2], h [j*4+3]);
    }
}

__global__ __launch_bounds__(256) void scanB_kernel()
{
    const int tid = blockIdx.x * 256 + threadIdx.x;   // 0..CSTATES-1
    float h = 0.f;
#pragma unroll 8
    for (int c = 0; c < N_CHK; ++c) {
        g_h0[c * CSTATES + tid] = h;
        h = fmaf(__ldg(&g_aP[c * CSTATES + tid]), h, __ldg(&g_hP[c * CSTATES + tid]));
    }
}

__global__ __launch_bounds__(128) void scanC_kernel(
    const float* __restrict__ Alog, const float* __restrict__ Dp)
{
    __shared__ float Bsh[T_CHK * DST];
    __shared__ float Csh[T_CHK * DST];

    const int tid = threadIdx.x;
    const int d   = blockIdx.x * 128 + tid;
    const int b   = blockIdx.y;
    const int chk = blockIdx.z;
    const int t0  = chk * T_CHK;
    const int ch  = b * SDIM + d;

    {
        const float4* srcB = reinterpret_cast<const float4*>(&g_Bm[((size_t)(b * L_SEQ + t0)) * DST]);
        const float4* srcC = reinterpret_cast<const float4*>(&g_Cm[((size_t)(b * L_SEQ + t0)) * DST]);
        reinterpret_cast<float4*>(Bsh)[tid] = __ldg(&srcB[tid]);
        reinterpret_cast<float4*>(Csh)[tid] = __ldg(&srcC[tid]);
    }

    float A[DST], h[DST];
#pragma unroll
    for (int n = 0; n < DST; ++n)
        A[n] = -expf(__ldg(&Alog[d * DST + n]));
    {
        const size_t hb = (size_t)chk * CSTATES + (size_t)ch * DST;
#pragma unroll
        for (int j = 0; j < 4; ++j) {
            float4 v = *reinterpret_cast<const float4*>(&g_h0[hb + j*4]);
            h[j*4+0] = v.x; h[j*4+1] = v.y; h[j*4+2] = v.z; h[j*4+3] = v.w;
        }
    }
    const float Dd = __ldg(&Dp[d]);
    __syncthreads();

    size_t ix = ((size_t)(b * L_SEQ + t0)) * SDIM + d;
#pragma unroll 4
    for (int t = 0; t < T_CHK; ++t) {
        float dt = __ldg(&g_dsp[ix]);
        float xv = __ldg(&g_xin[ix]);
        float u  = dt * xv;
        float p  = xv * Dd;
        const float4* Bq = reinterpret_cast<const float4*>(&Bsh[t * DST]);
        const float4* Cq = reinterpret_cast<const float4*>(&Csh[t * DST]);
#pragma unroll
        for (int j = 0; j < 4; ++j) {
            float4 bv = Bq[j];
            float4 cv = Cq[j];
            float e0 = __expf(dt * A[j*4+0]);
            float e1 = __expf(dt * A[j*4+1]);
            float e2 = __expf(dt * A[j*4+2]);
            float e3 = __expf(dt * A[j*4+3]);
            h[j*4+0] = fmaf(e0, h[j*4+0], u * bv.x);
            h[j*4+1] = fmaf(e1, h[j*4+1], u * bv.y);
            h[j*4+2] = fmaf(e2, h[j*4+2], u * bv.z);
            h[j*4+3] = fmaf(e3, h[j*4+3], u * bv.w);
            p = fmaf(h[j*4+0], cv.x, p);
            p = fmaf(h[j*4+1], cv.y, p);
            p = fmaf(h[j*4+2], cv.z, p);
            p = fmaf(h[j*4+3], cv.w, p);
        }
        g_y[ix] = p;
        ix += SDIM;
    }
}

// =========================================================================
// out GEMM: (16384,384) @ (384,384)^T + bias, transposed coalesced store
// =========================================================================
__global__ __launch_bounds__(256) void out_kernel(
    const float* __restrict__ Wo, const float* __restrict__ bo,
    float* __restrict__ out)
{
    __shared__ float As[2][16 * SSTR];
    __shared__ float Bs[2][16 * SSTR];

    const int tid = threadIdx.x;
    const int tx  = tid & 15;
    const int ty  = tid >> 4;
    const int m0  = blockIdx.x * 128;
    const int n0  = blockIdx.y * 128;
    const int b   = m0 >> 12;
    const int l0  = m0 & 4095;

    float4 Ar[2], Br[2];
    auto ldg = [&](int k0) {
#pragma unroll
        for (int r = 0; r < 2; ++r) {
            int q = tid + r * 256;
            int m = q >> 2, k4 = (q & 3) << 2;
            Ar[r] = *reinterpret_cast<const float4*>(&g_y[(size_t)(m0 + m) * SDIM + k0 + k4]);
            int n = q >> 2;
            Br[r] = *reinterpret_cast<const float4*>(&Wo[(size_t)(n0 + n) * SDIM + k0 + k4]);
        }
    };
    auto sts = [&](int buf) {
#pragma unroll
        for (int r = 0; r < 2; ++r) {
            int q = tid + r * 256;
            int m = q >> 2, k4 = (q & 3) << 2;
            As[buf][(k4 + 0) * SSTR + m] = Ar[r].x;
            As[buf][(k4 + 1) * SSTR + m] = Ar[r].y;
            As[buf][(k4 + 2) * SSTR + m] = Ar[r].z;
            As[buf][(k4 + 3) * SSTR + m] = Ar[r].w;
            Bs[buf][(k4 + 0) * SSTR + m] = Br[r].x;
            Bs[buf][(k4 + 1) * SSTR + m] = Br[r].y;
            Bs[buf][(k4 + 2) * SSTR + m] = Br[r].z;
            Bs[buf][(k4 + 3) * SSTR + m] = Br[r].w;
        }
    };

    float acc[8][8];
#pragma unroll
    for (int i = 0; i < 8; ++i)
#pragma unroll
        for (int j = 0; j < 8; ++j) acc[i][j] = 0.f;

    ldg(0);
    sts(0);
    __syncthreads();

    const int KT = SDIM / 16;
    for (int kt = 0; kt < KT; ++kt) {
        int cur = kt & 1;
        if (kt + 1 < KT) ldg((kt + 1) * 16);
#pragma unroll
        for (int k = 0; k < 16; ++k) {
            float a[8], bb[8];
            float4 a0 = *reinterpret_cast<const float4*>(&As[cur][k * SSTR + ty * 8]);
            float4 a1 = *reinterpret_cast<const float4*>(&As[cur][k * SSTR + ty * 8 + 4]);
            float4 b0 = *reinterpret_cast<const float4*>(&Bs[cur][k * SSTR + tx * 8]);
            float4 b1 = *reinterpret_cast<const float4*>(&Bs[cur][k * SSTR + tx * 8 + 4]);
            a[0]=a0.x;a[1]=a0.y;a[2]=a0.z;a[3]=a0.w;a[4]=a1.x;a[5]=a1.y;a[6]=a1.z;a[7]=a1.w;
            bb[0]=b0.x;bb[1]=b0.y;bb[2]=b0.z;bb[3]=b0.w;bb[4]=b1.x;bb[5]=b1.y;bb[6]=b1.z;bb[7]=b1.w;
#pragma unroll
            for (int i = 0; i < 8; ++i)
#pragma unroll
                for (int j = 0; j < 8; ++j)
                    acc[i][j] = fmaf(a[i], bb[j], acc[i][j]);
        }
        if (kt + 1 < KT) {
            sts(cur ^ 1);
            __syncthreads();
        }
    }

#pragma unroll
    for (int j = 0; j < 8; ++j) {
        const int n = n0 + tx * 8 + j;
        const float bj = bo[n];
        float* dst = &out[((size_t)(b * SDIM + n)) * L_SEQ + l0 + ty * 8];
        float4 v0 = make_float4(acc[0][j]+bj, acc[1][j]+bj, acc[2][j]+bj, acc[3][j]+bj);
        float4 v1 = make_float4(acc[4][j]+bj, acc[5][j]+bj, acc[6][j]+bj, acc[7][j]+bj);
        *reinterpret_cast<float4*>(dst)     = v0;
        *reinterpret_cast<float4*>(dst + 4) = v1;
    }
}

extern "C" void kernel_launch(void* const* d_in, const int* in_sizes, int n_in,
                              void* d_out, int out_size)
{
    const float* x    = (const float*)d_in[0];
    const float* Wp   = (const float*)d_in[1];
    const float* bp   = (const float*)d_in[2];
    const float* Alog = (const float*)d_in[3];
    const float* D    = (const float*)d_in[4];
    const float* dtb  = (const float*)d_in[5];
    const float* Wo   = (const float*)d_in[6];
    const float* bo   = (const float*)d_in[7];
    float* out = (float*)d_out;

    dim3 g1(M_TOT / 128, (P_TOT + 127) / 128);   // (128, 7)
    proj_kernel<<<g1, 256>>>(x, Wp, bp, dtb);

    dim3 gs(SDIM / 128, BATCH, N_CHK);           // (3, 4, 128) = 1536 blocks
    scanA_kernel<<<gs, 128>>>(Alog);
    scanB_kernel<<<CSTATES / 256, 256>>>();
    scanC_kernel<<<gs, 128>>>(Alog, D);

    dim3 g2(M_TOT / 128, SDIM / 128);            // (128, 3)
    out_kernel<<<g2, 256>>>(Wo, bo, out);
}